// round 4
// baseline (speedup 1.0000x reference)
#include <cuda_runtime.h>

// ---------------------------------------------------------------------------
// Causal spectral filter: out = irfft(rfft(x,16384) * spec)[..., :8192, :]
// 8192-pt complex FFT decomposed [16,16,16,2]: radix-16 stages in registers,
// smem only for inter-stage exchange; final radix-2 via warp shuffle.
// fwd: natural in -> digit-rev out; inv: exact mirror. Pointwise filter is
// register-fused between fwd end and inv start.
// ---------------------------------------------------------------------------

#define IDX(i) ((i) + ((i) >> 4))     // smem pad: conflict-free for all stages

static __device__ float  g_xt[8u * 512u * 8192u];   // x transposed (B,D,N)
static __device__ float  g_yt[8u * 512u * 8192u];   // y transposed (B,D,N)
static __device__ float2 g_spec[512u * 8200u];      // per-channel spectrum (natural k)
static __device__ float2 g_tw[1024];                // W_8192^c, c<1024

__device__ __forceinline__ float2 cadd(float2 a, float2 b) { return make_float2(a.x + b.x, a.y + b.y); }
__device__ __forceinline__ float2 csub(float2 a, float2 b) { return make_float2(a.x - b.x, a.y - b.y); }
__device__ __forceinline__ float2 cmul(float2 a, float2 b) {
    return make_float2(fmaf(a.x, b.x, -a.y * b.y), fmaf(a.x, b.y, a.y * b.x));
}
__device__ __forceinline__ float2 cmulc(float2 a, float2 b) {   // a * conj(b)
    return make_float2(fmaf(a.x, b.x,  a.y * b.y), fmaf(a.y, b.x, -a.x * b.y));
}
template <int S>
__device__ __forceinline__ float2 crot(float2 z) {   // multiply by S*i
    return (S < 0) ? make_float2(z.y, -z.x) : make_float2(-z.y, z.x);
}
__device__ __forceinline__ float2 shfl_xor_f2(float2 v, int m) {
    return make_float2(__shfl_xor_sync(0xffffffffu, v.x, m),
                       __shfl_xor_sync(0xffffffffu, v.y, m));
}

// digit-reverse for radices [16,16,16,2] (subs 512,32,2,1)
__device__ __forceinline__ int drev(int k) {
    return ((k & 15) << 9) | (((k >> 4) & 15) << 5) | (((k >> 8) & 15) << 1) | (k >> 12);
}
// output slot permutation of in-register radix-16 (involution)
__host__ __device__ constexpr int P16(int k) { return ((k & 3) << 2) | (k >> 2); }

// W_16384^k for 0<=k<8192 from the 1024-entry table
__device__ __forceinline__ float2 tw16384(const float2* T, int k) {
    int a = k >> 1;
    float2 w = T[a & 1023];
    int u = (a >> 10) & 3;
    const float S2 = 0.70710678118654752f;
    if (u & 2) w = make_float2(w.y, -w.x);                       // * -i
    if (u & 1) w = cmul(w, make_float2(S2, -S2));                // * W_8^1
    if (k & 1) w = cmul(w, make_float2(0.99999992646571789f, -3.8349518757139556e-4f));
    return w;
}

template <int SGN>
__device__ __forceinline__ void r4(float2& a, float2& b, float2& c, float2& d) {
    float2 t0 = cadd(a, c), t1 = csub(a, c), t2 = cadd(b, d), t3 = csub(b, d);
    float2 m = crot<SGN>(t3);
    a = cadd(t0, t2); b = cadd(t1, m); c = csub(t0, t2); d = csub(t1, m);
}

template <int SGN>
__device__ __forceinline__ void bfly16_tail(float2 v[16]) {
    const float C1 = 0.92387953251128674f;
    const float S1 = 0.38268343236508978f;
    const float R2 = 0.70710678118654752f;
    const float2 w1 = make_float2(C1, SGN * S1);
    const float2 w2 = make_float2(R2, SGN * R2);
    const float2 w3 = make_float2(S1, SGN * C1);
    const float2 w6 = make_float2(-R2, SGN * R2);
    const float2 w9 = make_float2(-C1, -SGN * S1);
    v[5]  = cmul(v[5],  w1);   // r=1,s=1
    v[9]  = cmul(v[9],  w2);   // r=1,s=2
    v[13] = cmul(v[13], w3);   // r=1,s=3
    v[6]  = cmul(v[6],  w2);   // r=2,s=1
    v[10] = crot<SGN>(v[10]);  // r=2,s=2 (e=4)
    v[14] = cmul(v[14], w6);   // r=2,s=3
    v[7]  = cmul(v[7],  w3);   // r=3,s=1
    v[11] = cmul(v[11], w6);   // r=3,s=2
    v[15] = cmul(v[15], w9);   // r=3,s=3
#pragma unroll
    for (int s = 0; s < 4; s++) r4<SGN>(v[4*s], v[4*s+1], v[4*s+2], v[4*s+3]);
}

// full 16-pt DFT: input A[i]=v[i], output X[k] at v[P16(k)]
template <int SGN>
__device__ __forceinline__ void bfly16(float2 v[16]) {
#pragma unroll
    for (int r = 0; r < 4; r++) r4<SGN>(v[r], v[r+4], v[r+8], v[r+12]);
    bfly16_tail<SGN>(v);
}

// same, with inputs v[8..15] known zero (only v[0..7] read)
template <int SGN>
__device__ __forceinline__ void bfly16hz(float2 v[16]) {
#pragma unroll
    for (int r = 0; r < 4; r++) {
        float2 a = v[r], b = v[r+4];
        float2 m = crot<SGN>(b);
        v[r]    = cadd(a, b);
        v[r+4]  = cadd(a, m);
        v[r+8]  = csub(a, b);
        v[r+12] = csub(a, m);
    }
    bfly16_tail<SGN>(v);
}

// ---- stage helpers (512 threads) ------------------------------------------

// fwd stage1 from registers a[i] (A[i] at a[i]); writes twiddled to buf
__device__ __forceinline__ void fwd_s1_store(float2 a[16], float2* buf, const float2* T, int t) {
    float2 w1 = T[t];
    buf[IDX(t)] = a[0];
    float2 w = w1;
    buf[IDX(t + 512)] = cmul(a[P16(1)], w);
#pragma unroll
    for (int r = 2; r < 16; r++) { w = cmul(w, w1); buf[IDX(t + (r << 9))] = cmul(a[P16(r)], w); }
}

__device__ __forceinline__ void fwd_s2(float2* buf, const float2* T, int t) {
    int base = ((t >> 5) << 9) + (t & 31);
    float2 v[16];
#pragma unroll
    for (int i = 0; i < 16; i++) v[i] = buf[IDX(base + (i << 5))];
    bfly16<-1>(v);
    float2 w1 = T[(t & 31) << 4];
    buf[IDX(base)] = v[0];
    float2 w = w1;
    buf[IDX(base + 32)] = cmul(v[P16(1)], w);
#pragma unroll
    for (int r = 2; r < 16; r++) { w = cmul(w, w1); buf[IDX(base + (r << 5))] = cmul(v[P16(r)], w); }
}

// fwd stage3 + radix-2 shuffle; leaves final values (digit-rev layout) in u and buf
__device__ __forceinline__ void fwd_s3_r2(float2* buf, const float2* T, int t, float2 u[16]) {
    int g = t >> 1, j = t & 1;
    int base = (g << 5) + j;
    float2 v[16];
#pragma unroll
    for (int i = 0; i < 16; i++) v[i] = buf[IDX(base + (i << 1))];
    bfly16<-1>(v);
    float2 w1 = j ? T[256] : make_float2(1.f, 0.f);
    u[0] = v[0];
    float2 w = w1;
    u[1] = cmul(v[P16(1)], w);
#pragma unroll
    for (int r = 2; r < 16; r++) { w = cmul(w, w1); u[r] = cmul(v[P16(r)], w); }
#pragma unroll
    for (int r = 0; r < 16; r++) {
        float2 o = shfl_xor_f2(u[r], 1);
        u[r] = j ? csub(o, u[r]) : cadd(u[r], o);
    }
#pragma unroll
    for (int r = 0; r < 16; r++) buf[IDX((g << 5) + (r << 1) + j)] = u[r];
}

// inverse: shuffle radix-2 + untwiddle + conj radix-16; writes stage-input positions
__device__ __forceinline__ void inv_s3(float2 z[16], float2* buf, const float2* T, int t) {
    int g = t >> 1, j = t & 1;
#pragma unroll
    for (int r = 0; r < 16; r++) {
        float2 o = shfl_xor_f2(z[r], 1);
        z[r] = j ? csub(o, z[r]) : cadd(z[r], o);
    }
    float2 w1 = j ? T[256] : make_float2(1.f, 0.f);
    float2 v[16];
    v[0] = z[0];
    float2 w = w1;
    v[1] = cmulc(z[1], w);
#pragma unroll
    for (int r = 2; r < 16; r++) { w = cmul(w, w1); v[r] = cmulc(z[r], w); }
    bfly16<1>(v);
    int base = (g << 5) + j;
#pragma unroll
    for (int i = 0; i < 16; i++) buf[IDX(base + (i << 1))] = v[P16(i)];
}

__device__ __forceinline__ void inv_s2(float2* buf, const float2* T, int t) {
    int base = ((t >> 5) << 9) + (t & 31);
    float2 w1 = T[(t & 31) << 4];
    float2 v[16];
    v[0] = buf[IDX(base)];
    float2 w = w1;
    v[1] = cmulc(buf[IDX(base + 32)], w);
#pragma unroll
    for (int r = 2; r < 16; r++) { w = cmul(w, w1); v[r] = cmulc(buf[IDX(base + (r << 5))], w); }
    bfly16<1>(v);
#pragma unroll
    for (int i = 0; i < 16; i++) buf[IDX(base + (i << 5))] = v[P16(i)];
}

// inverse stage1: natural value of index (t+512*i) ends at v[P16(i)]
__device__ __forceinline__ void inv_s1_reg(float2* buf, const float2* T, int t, float2 v[16]) {
    float2 w1 = T[t];
    v[0] = buf[IDX(t)];
    float2 w = w1;
    v[1] = cmulc(buf[IDX(t + 512)], w);
#pragma unroll
    for (int r = 2; r < 16; r++) { w = cmul(w, w1); v[r] = cmulc(buf[IDX(t + (r << 9))], w); }
    bfly16<1>(v);
}

// ---------------------------------------------------------------------------

__global__ void k_tw() {
    int j = blockIdx.x * blockDim.x + threadIdx.x;
    if (j < 1024) {
        double a = -2.0 * 3.14159265358979323846264338327950288 * (double)j / 8192.0;
        g_tw[j] = make_float2((float)cos(a), (float)sin(a));
    }
}

__global__ void k_tin(const float* __restrict__ x) {
    __shared__ float tile[32][33];
    int b = blockIdx.z;
    int d0 = blockIdx.x << 5, n0 = blockIdx.y << 5;
    int tx = threadIdx.x, ty = threadIdx.y;
    const float* xb = x + (size_t)b * 8192u * 512u;
#pragma unroll
    for (int i = ty; i < 32; i += 8)
        tile[i][tx] = xb[(size_t)(n0 + i) * 512u + d0 + tx];
    __syncthreads();
    float* xt = g_xt + (size_t)b * 512u * 8192u;
#pragma unroll
    for (int i = ty; i < 32; i += 8)
        xt[(size_t)(d0 + i) * 8192u + n0 + tx] = tile[tx][i];
}

__global__ void k_tout(float* __restrict__ out) {
    __shared__ float tile[32][33];
    int b = blockIdx.z;
    int d0 = blockIdx.x << 5, n0 = blockIdx.y << 5;
    int tx = threadIdx.x, ty = threadIdx.y;
    const float* yt = g_yt + (size_t)b * 512u * 8192u;
#pragma unroll
    for (int i = ty; i < 32; i += 8)
        tile[i][tx] = yt[(size_t)(d0 + i) * 8192u + n0 + tx];
    __syncthreads();
#pragma unroll
    for (int i = ty; i < 32; i += 8)
        out[((size_t)b * 8192u + n0 + i) * 512u + d0 + tx] = tile[tx][i];
}

// Per-channel spectrum build
__global__ void __launch_bounds__(512, 2) k_filter(const float* __restrict__ coeffs,
                                                   const float* __restrict__ dc) {
    extern __shared__ float2 sm[];
    float2* buf = sm;                       // 8704
    float2* T   = sm + 8704;                // 1024
    float*  cf  = (float*)(sm + 9728);      // 512 floats
    int d = blockIdx.x;
    int t = threadIdx.x;
    T[t] = g_tw[t];
    T[t + 512] = g_tw[t + 512];
    cf[t] = coeffs[d * 512 + t];
    float dcv = dc[d];
    __syncthreads();

    auto interp = [&](int k) -> float {
        if (k == 0) return dcv;
        float src = ((float)k - 0.5f) * 0.0625f - 0.5f;
        src = fminf(fmaxf(src, 0.0f), 511.0f);
        int lo = (int)src;
        int hi = min(lo + 1, 511);
        float w = src - (float)lo;
        float clo = cf[lo];
        return fmaf(cf[hi] - clo, w, clo);
    };

    int g = t >> 1, j = t & 1;
    int c = (g >> 4) + ((g & 15) << 4) + (j << 12);

    // Build Z(k) for this thread's coefficients k = c + 256*i (s3-layout regs)
    float2 z[16];
#pragma unroll
    for (int i = 0; i < 16; i++) {
        int k = c + (i << 8);
        float ak  = interp(k);
        float akk = interp(8192 - k);
        float fe = 0.5f * (ak + akk);
        float gg = 0.5f * (ak - akk);
        float2 t2 = tw16384(T, k);
        z[i] = make_float2(fmaf(t2.y, gg, fe), t2.x * gg);
    }
    // inverse FFT (unnormalized): digit-rev regs -> natural regs
    inv_s3(z, buf, T, t);  __syncthreads();
    inv_s2(buf, T, t);     __syncthreads();
    float2 v[16];
    inv_s1_reg(buf, T, t, v);

    // analytic window + 1/8192
    const float inv = 1.0f / 8192.0f;
    float2 a[16];
#pragma unroll
    for (int i = 0; i < 16; i++) {
        float2 zz = v[P16(i)];
        int n = t + (i << 9);
        float sx, sy;
        if (n == 0)         { sx = inv;        sy = 2.0f * inv; }
        else if (n < 4096)  { sx = 2.0f * inv; sy = 2.0f * inv; }
        else if (n == 4096) { sx = inv;        sy = 0.0f; }
        else                { sx = 0.0f;       sy = 0.0f; }
        a[i] = make_float2(zz.x * sx, zz.y * sy);
    }
    // forward FFT
    bfly16<-1>(a);
    fwd_s1_store(a, buf, T, t);  __syncthreads();
    fwd_s2(buf, T, t);           __syncthreads();
    float2 u[16];
    fwd_s3_r2(buf, T, t, u);     __syncthreads();

    // uniform sweep: real-spectrum split -> sp[0..8192]
    float2* sp = g_spec + (size_t)d * 8200u;
    for (int k = t; k <= 8192; k += 512) {
        float2 r;
        if (k == 0) {
            float2 Z0 = buf[IDX(0)];
            r = make_float2(Z0.x + Z0.y, 0.0f);
        } else if (k == 8192) {
            float2 Z0 = buf[IDX(0)];
            r = make_float2(Z0.x - Z0.y, 0.0f);
        } else if (k == 4096) {
            float2 Z4 = buf[IDX(1)];            // drev(4096) = 1
            r = make_float2(Z4.x, -Z4.y);
        } else {
            float2 P = buf[IDX(drev(k))];
            float2 Q = buf[IDX(drev(8192 - k))];
            float2 Fe = make_float2(0.5f * (P.x + Q.x), 0.5f * (P.y - Q.y));
            float2 Fo = make_float2(0.5f * (P.y + Q.y), -0.5f * (P.x - Q.x));
            float2 t2 = tw16384(T, k);
            r = cadd(Fe, cmul(t2, Fo));
        }
        sp[k] = r;
    }
}

// Per (b,d): rfft(x row) * spec -> irfft -> first 8192 samples
__global__ void __launch_bounds__(512, 2) k_conv() {
    extern __shared__ float2 sm[];
    float2* buf = sm;                       // 8704
    float2* T   = sm + 8704;                // 1024
    int bid = blockIdx.x;
    int d = bid & 511;
    int b = bid >> 9;
    int t = threadIdx.x;
    T[t] = g_tw[t];
    T[t + 512] = g_tw[t + 512];
    __syncthreads();

    // forward: stage1 from gmem (upper half zero)
    const float2* xr = (const float2*)(g_xt + ((size_t)(b * 512 + d) << 13));
    {
        float2 a[16];
#pragma unroll
        for (int i = 0; i < 8; i++) a[i] = xr[t + (i << 9)];
        bfly16hz<-1>(a);
        fwd_s1_store(a, buf, T, t);
    }
    __syncthreads();
    fwd_s2(buf, T, t);  __syncthreads();
    float2 u[16];
    fwd_s3_r2(buf, T, t, u);  __syncthreads();

    // pointwise filter (register-fused): thread owns k = c + 256*i
    int g = t >> 1, j = t & 1;
    int c = (g >> 4) + ((g & 15) << 4) + (j << 12);
    const float2* sp = g_spec + (size_t)d * 8200u;
#pragma unroll
    for (int i = 0; i < 16; i++) {
        int k = c + (i << 8);
        float2 P = u[i];
        float2 z;
        if (k == 0) {
            float X0 = P.x + P.y, XN = P.x - P.y;
            float Y0 = X0 * sp[0].x, YN = XN * sp[8192].x;
            z = make_float2(0.5f * (Y0 + YN), 0.5f * (Y0 - YN));
        } else if (k == 4096) {
            float2 X4 = make_float2(P.x, -P.y);
            float2 Y4 = cmul(X4, sp[4096]);
            z = make_float2(Y4.x, -Y4.y);
        } else {
            int kk = 8192 - k;
            float2 Q = buf[IDX(drev(kk))];
            float2 Fe = make_float2(0.5f * (P.x + Q.x), 0.5f * (P.y - Q.y));
            float2 Fo = make_float2(0.5f * (P.y + Q.y), -0.5f * (P.x - Q.x));
            float2 t2 = tw16384(T, k);
            float2 Xk  = cadd(Fe, cmul(t2, Fo));
            float2 cFe = make_float2(Fe.x, -Fe.y);
            float2 cFo = make_float2(Fo.x, -Fo.y);
            float2 nt  = make_float2(-t2.x, t2.y);          // W_16384^kk
            float2 Xkk = cadd(cFe, cmul(nt, cFo));
            float2 Yk  = cmul(Xk,  sp[k]);
            float2 Ykk = cmul(Xkk, sp[kk]);
            float2 Fe2 = make_float2(0.5f * (Yk.x + Ykk.x), 0.5f * (Yk.y - Ykk.y));
            float2 hd  = make_float2(0.5f * (Yk.x - Ykk.x), 0.5f * (Yk.y + Ykk.y));
            float2 ct2 = make_float2(t2.x, -t2.y);
            float2 Fo2 = cmul(ct2, hd);
            z = make_float2(Fe2.x - Fo2.y, Fe2.y + Fo2.x);
        }
        u[i] = z;
    }
    __syncthreads();   // all partner reads done before inverse overwrites buf

    // inverse
    inv_s3(u, buf, T, t);  __syncthreads();
    inv_s2(buf, T, t);     __syncthreads();
    float2 v[16];
    inv_s1_reg(buf, T, t, v);

    const float inv = 1.0f / 8192.0f;
    float2* yr = (float2*)(g_yt + ((size_t)(b * 512 + d) << 13));
#pragma unroll
    for (int i = 0; i < 8; i++) {
        float2 w = v[P16(i)];
        yr[t + (i << 9)] = make_float2(w.x * inv, w.y * inv);
    }
}

// ---------------------------------------------------------------------------

extern "C" void kernel_launch(void* const* d_in, const int* in_sizes, int n_in,
                              void* d_out, int out_size) {
    const float* x      = (const float*)d_in[0];
    const float* coeffs = (const float*)d_in[1];
    const float* dc     = (const float*)d_in[2];
    float* out = (float*)d_out;

    size_t smem_c = 9728u * sizeof(float2);            // 77824
    size_t smem_f = smem_c + 512u * sizeof(float);     // 79872
    cudaFuncSetAttribute(k_filter, cudaFuncAttributeMaxDynamicSharedMemorySize, (int)smem_f);
    cudaFuncSetAttribute(k_conv,   cudaFuncAttributeMaxDynamicSharedMemorySize, (int)smem_c);

    k_tw<<<2, 512>>>();
    k_tin<<<dim3(16, 256, 8), dim3(32, 8)>>>(x);
    k_filter<<<512, 512, smem_f>>>(coeffs, dc);
    k_conv<<<4096, 512, smem_c>>>();
    k_tout<<<dim3(16, 256, 8), dim3(32, 8)>>>(out);
}